// round 14
// baseline (speedup 1.0000x reference)
#include <cuda_runtime.h>

#define EPSF 1e-6f

__device__ __forceinline__ int tri(int i, int j) { return i * (i + 1) / 2 + j; } // j<=i

// Symmetric 8x8 stored as lower-tri 36; all uses have compile-time indices.
#define AS(i, j) As[((i) >= (j)) ? ((i) * ((i) + 1) / 2 + (j)) : ((j) * ((j) + 1) / 2 + (i))]

// dst (SET? =: +=) w * rho_norm(row).  Low register pressure: diag Gram first ->
// trace -> scale, then stream off-diagonals straight into dst.
template <bool SET>
__device__ __forceinline__ void density_go(const float4* __restrict__ row, float w,
                                           float* __restrict__ dst) {
    float p[36];
#pragma unroll
    for (int v = 0; v < 9; v++) {
        float4 q = __ldg(row + v);
        p[4 * v + 0] = q.x; p[4 * v + 1] = q.y; p[4 * v + 2] = q.z; p[4 * v + 3] = q.w;
    }
#pragma unroll
    for (int i = 0; i < 8; i++) p[tri(i, i)] = fmaxf(p[tri(i, i)], 1e-4f);

    float diag[8];
    float trs = 0.f;
#pragma unroll
    for (int i = 0; i < 8; i++) {
        float s = 0.f;
#pragma unroll
        for (int k = 0; k <= i; k++) s = fmaf(p[tri(i, k)], p[tri(i, k)], s);
        diag[i] = s;
        trs += s;
    }
    // corr = 1e-6 always (rho = LL^T + eps*I is PD) -> diag shift eps+1e-6 = 2e-6
    float inv = w * __fdividef(1.f, trs + 8.f * 2e-6f + EPSF);

#pragma unroll
    for (int i = 0; i < 8; i++) {
        float v = inv * (diag[i] + 2e-6f);
        dst[tri(i, i)] = SET ? v : (dst[tri(i, i)] + v);
    }
#pragma unroll
    for (int i = 1; i < 8; i++) {
#pragma unroll
        for (int j = 0; j < i; j++) {
            float s = 0.f;
#pragma unroll
            for (int k = 0; k <= j; k++) s = fmaf(p[tri(i, k)], p[tri(j, k)], s);
            float v = inv * s;
            dst[tri(i, j)] = SET ? v : (dst[tri(i, j)] + v);
        }
    }
}

// One tournament round of the quad-parallel Jacobi. r must be a compile-time
// constant at every call site (unrolled loops) so all indexing stays in registers.
__device__ __forceinline__ void jround(float* __restrict__ As, int r,
                                       bool is1, bool is2, bool is3) {
    const int JP[7][4] = {{0,1,2,3},{0,2,3,4},{0,1,4,5},{0,2,1,6},{0,3,2,1},{0,4,3,1},{0,5,1,2}};
    const int JQ[7][4] = {{7,6,5,4},{1,7,6,5},{2,3,7,6},{3,4,5,7},{4,5,6,7},{5,6,7,2},{6,7,4,3}};

    // select this lane's (app, aqq, apq) -- compile-time indices + SEL tree
    float app, aqq, apq;
    {
        float x0 = As[tri(JP[r][0], JP[r][0])], x1 = As[tri(JP[r][1], JP[r][1])];
        float x2 = As[tri(JP[r][2], JP[r][2])], x3 = As[tri(JP[r][3], JP[r][3])];
        app = is3 ? x3 : (is2 ? x2 : (is1 ? x1 : x0));
        float y0 = As[tri(JQ[r][0], JQ[r][0])], y1 = As[tri(JQ[r][1], JQ[r][1])];
        float y2 = As[tri(JQ[r][2], JQ[r][2])], y3 = As[tri(JQ[r][3], JQ[r][3])];
        aqq = is3 ? y3 : (is2 ? y2 : (is1 ? y1 : y0));
        float z0 = As[tri(JQ[r][0], JP[r][0])], z1 = As[tri(JQ[r][1], JP[r][1])];
        float z2 = As[tri(JQ[r][2], JP[r][2])], z3 = As[tri(JQ[r][3], JP[r][3])];
        apq = is3 ? z3 : (is2 ? z2 : (is1 ? z1 : z0));
    }
    // one rotation-parameter chain per lane
    float theta = __fdividef(aqq - app, 2.f * apq);
    float t = __fdividef(1.f, fabsf(theta) + sqrtf(fmaf(theta, theta, 1.f)));
    t = copysignf(t, theta);
    t = (fabsf(apq) > 1e-30f) ? t : 0.f;   // also kills NaN theta (0/0)
    float c = rsqrtf(fmaf(t, t, 1.f));
    float s = t * c;
    float d = t * apq;

    // exchange (c, s, d) across the quad
    float cj[4], sj[4], dj[4];
#pragma unroll
    for (int j = 0; j < 4; j++) {
        cj[j] = __shfl_sync(0xffffffffu, c, j, 4);
        sj[j] = __shfl_sync(0xffffffffu, s, j, 4);
        dj[j] = __shfl_sync(0xffffffffu, d, j, 4);
    }

    // every lane applies all 4 disjoint rotations to its copy of As
#pragma unroll
    for (int i = 0; i < 4; i++) {
        int p = JP[r][i], q = JQ[r][i];
        As[tri(p, p)] -= dj[i];
        As[tri(q, q)] += dj[i];
        As[tri(q, p)] = 0.f;                  // p<q
    }
#pragma unroll
    for (int i = 0; i < 4; i++) {
#pragma unroll
        for (int j = i + 1; j < 4; j++) {
            int pi = JP[r][i], qi = JQ[r][i];
            int pj = JP[r][j], qj = JQ[r][j];
            float a00 = AS(pi, pj), a01 = AS(pi, qj);
            float a10 = AS(qi, pj), a11 = AS(qi, qj);
            // rows (G_i^T)
            float b00 = fmaf(cj[i], a00, -sj[i] * a10);
            float b01 = fmaf(cj[i], a01, -sj[i] * a11);
            float b10 = fmaf(sj[i], a00,  cj[i] * a10);
            float b11 = fmaf(sj[i], a01,  cj[i] * a11);
            // cols (G_j)
            float n00 = fmaf(cj[j], b00, -sj[j] * b01);
            float n01 = fmaf(sj[j], b00,  cj[j] * b01);
            float n10 = fmaf(cj[j], b10, -sj[j] * b11);
            float n11 = fmaf(sj[j], b10,  cj[j] * b11);
            AS(pi, pj) = n00; AS(pi, qj) = n01;
            AS(qi, pj) = n10; AS(qi, qj) = n11;
        }
    }
}

// ---------------- cooperative kernel: 4 lanes per batch element (S == 10) ----------------
__global__ void __launch_bounds__(128, 4) qcbow_quad(
    const int* __restrict__ contexts,   // [B, 10]
    const int* __restrict__ targets,    // [B]
    const float* __restrict__ emb,      // [V, 36]
    float* __restrict__ out,            // [B]
    int B)
{
    const int S = 10;
    int tid = blockIdx.x * 128 + threadIdx.x;
    int b   = tid >> 2;
    int sub = tid & 3;
    bool active = (b < B);
    if (!active) b = 0;               // keep all lanes alive for shuffles

    float acc[36], sigma[36];
    float cnt;

    // ---- phase 1: tokens 0..7 split across the quad; iteration 3 is fused:
    //      lanes 0,1 take tokens 8,9; lanes 2,3 compute the target density. ----
    {
        int tok = contexts[b * S + sub];
        float w = (tok != 0) ? 1.f : 0.f;
        cnt = w;
        density_go<true>((const float4*)(emb + (size_t)tok * 36u), w, acc);
    }
    {
        int tok = contexts[b * S + 4 + sub];
        float w = (tok != 0) ? 1.f : 0.f;
        cnt += w;
        density_go<false>((const float4*)(emb + (size_t)tok * 36u), w, acc);
    }
    {
        bool ctx = (sub < 2);
        const int* addr = ctx ? (contexts + b * S + 8 + sub) : (targets + b);
        int tok = __ldg(addr);
        float w = ctx ? ((tok != 0) ? 1.f : 0.f) : 1.f;
        cnt += ctx ? w : 0.f;
        float tmp[36];
        density_go<true>((const float4*)(emb + (size_t)tok * 36u), w, tmp);
        float m = ctx ? 1.f : 0.f;
#pragma unroll
        for (int i = 0; i < 36; i++) acc[i] = fmaf(m, tmp[i], acc[i]);
        // sigma: lanes 2,3 computed the (identical) target density; broadcast lane 2
#pragma unroll
        for (int i = 0; i < 36; i++) sigma[i] = __shfl_sync(0xffffffffu, tmp[i], 2, 4);
    }

    // butterfly reduce within the quad; all 4 lanes end bitwise identical
#pragma unroll
    for (int i = 0; i < 36; i++) {
        acc[i] += __shfl_xor_sync(0xffffffffu, acc[i], 1);
        acc[i] += __shfl_xor_sync(0xffffffffu, acc[i], 2);
    }
    cnt += __shfl_xor_sync(0xffffffffu, cnt, 1);
    cnt += __shfl_xor_sync(0xffffffffu, cnt, 2);

    // ---- Cholesky of rho_bar + eps*I, in place in acc (lower C) ----
    {
        float invc = __fdividef(1.f, cnt);
#pragma unroll
        for (int i = 0; i < 36; i++) acc[i] *= invc;
#pragma unroll
        for (int i = 0; i < 8; i++) acc[tri(i, i)] += EPSF;
#pragma unroll
        for (int j = 0; j < 8; j++) {
            float d = acc[tri(j, j)];
#pragma unroll
            for (int k = 0; k < j; k++) d = fmaf(-acc[tri(j, k)], acc[tri(j, k)], d);
            d = sqrtf(fmaxf(d, 1e-12f));
            acc[tri(j, j)] = d;
            float invd = __fdividef(1.f, d);
#pragma unroll
            for (int i = j + 1; i < 8; i++) {
                float v = acc[tri(i, j)];
#pragma unroll
                for (int k = 0; k < j; k++) v = fmaf(-acc[tri(i, k)], acc[tri(j, k)], v);
                acc[tri(i, j)] = v * invd;
            }
        }
    }

    // ---- As = C^T * sigma * C (symmetric, lower-tri storage);
    //      eig(As) = eig((rho_bar+eps I) sigma) ----
    float As[36];
#pragma unroll
    for (int bc = 0; bc < 8; bc++) {
        float tcol[8];
#pragma unroll
        for (int k = 0; k < 8; k++) {
            float s = 0.f;
#pragma unroll
            for (int m = 0; m < 8; m++) {
                if (m < bc) continue;                 // C[m][bc]==0 for m<bc
                float sg = (k >= m) ? sigma[tri(k, m)] : sigma[tri(m, k)];
                s = fmaf(sg, acc[tri(m, bc)], s);
            }
            tcol[k] = s;
        }
#pragma unroll
        for (int a = 0; a <= bc; a++) {
            float s = 0.f;
#pragma unroll
            for (int k = 0; k < 8; k++) {
                if (k < a) continue;                  // C[k][a]==0 for k<a
                s = fmaf(acc[tri(k, a)], tcol[k], s);
            }
            As[tri(bc, a)] = s;
        }
    }

    // ---- quad-parallel Jacobi: 3 full sweeps + 3 hedge rounds ----
    bool is1 = (sub == 1), is2 = (sub == 2), is3 = (sub == 3);
#pragma unroll 1
    for (int sweep = 0; sweep < 3; sweep++) {
#pragma unroll
        for (int r = 0; r < 7; r++) jround(As, r, is1, is2, is3);
    }
#pragma unroll
    for (int r = 0; r < 3; r++) jround(As, r, is1, is2, is3);

    // ---- f = sum sqrt(lambda + eps), clip, -log ----
    if (active && sub == 0) {
        float f = 0.f;
#pragma unroll
        for (int i = 0; i < 8; i++) f += sqrtf(fmaxf(As[tri(i, i)], 0.f) + EPSF);
        f = fminf(f, 1.f);
        out[b] = -logf(fmaxf(f, 1e-8f));
    }
}

// ---------------- Fallback: monolithic kernel for unexpected shapes ----------------
__global__ void __launch_bounds__(64) qcbow_fallback(
    const int* __restrict__ contexts, const int* __restrict__ targets,
    const float* __restrict__ emb, float* __restrict__ out, int B, int S)
{
    int b = blockIdx.x * blockDim.x + threadIdx.x;
    if (b >= B) return;

    float acc[36];
#pragma unroll
    for (int i = 0; i < 36; i++) acc[i] = 0.f;
    float cnt = 0.f;
#pragma unroll 1
    for (int s = 0; s < S; s++) {
        int tok = contexts[(long long)b * S + s];
        float w = (tok != 0) ? 1.f : 0.f;
        cnt += w;
        density_go<false>((const float4*)(emb + (size_t)tok * 36u), w, acc);
    }
    float sigma[36];
    density_go<true>((const float4*)(emb + (size_t)targets[b] * 36u), 1.f, sigma);

    float C[36];
    {
        float invc = __fdividef(1.f, cnt);
#pragma unroll
        for (int i = 0; i < 36; i++) C[i] = acc[i] * invc;
#pragma unroll
        for (int i = 0; i < 8; i++) C[tri(i, i)] += EPSF;
#pragma unroll
        for (int j = 0; j < 8; j++) {
            float d = C[tri(j, j)];
#pragma unroll
            for (int k = 0; k < j; k++) d = fmaf(-C[tri(j, k)], C[tri(j, k)], d);
            d = sqrtf(fmaxf(d, 1e-12f));
            C[tri(j, j)] = d;
            float invd = __fdividef(1.f, d);
#pragma unroll
            for (int i = j + 1; i < 8; i++) {
                float v = C[tri(i, j)];
#pragma unroll
                for (int k = 0; k < j; k++) v = fmaf(-C[tri(i, k)], C[tri(j, k)], v);
                C[tri(i, j)] = v * invd;
            }
        }
    }

    float A[8][8];
#pragma unroll
    for (int bc = 0; bc < 8; bc++) {
        float tcol[8];
#pragma unroll
        for (int k = 0; k < 8; k++) {
            float s = 0.f;
#pragma unroll
            for (int m = 0; m < 8; m++) {
                if (m < bc) continue;
                float sg = (k >= m) ? sigma[tri(k, m)] : sigma[tri(m, k)];
                s = fmaf(sg, C[tri(m, bc)], s);
            }
            tcol[k] = s;
        }
#pragma unroll
        for (int a = 0; a < 8; a++) {
            if (a > bc) continue;
            float s = 0.f;
#pragma unroll
            for (int k = 0; k < 8; k++) {
                if (k < a) continue;
                s = fmaf(C[tri(k, a)], tcol[k], s);
            }
            A[a][bc] = s; A[bc][a] = s;
        }
    }

#pragma unroll 1
    for (int sweep = 0; sweep < 6; sweep++) {
#pragma unroll
        for (int p = 0; p < 7; p++) {
#pragma unroll
            for (int q = p + 1; q < 8; q++) {
                float apq = A[p][q];
                float app = A[p][p], aqq = A[q][q];
                float theta = __fdividef(aqq - app, 2.f * apq);
                float t = __fdividef(1.f, fabsf(theta) + sqrtf(fmaf(theta, theta, 1.f)));
                t = copysignf(t, theta);
                t = (fabsf(apq) > 1e-30f) ? t : 0.f;
                float c = rsqrtf(fmaf(t, t, 1.f));
                float s = t * c;
                A[p][p] = fmaf(-t, apq, app);
                A[q][q] = fmaf(t, apq, aqq);
                A[p][q] = 0.f; A[q][p] = 0.f;
#pragma unroll
                for (int k = 0; k < 8; k++) {
                    if (k == p || k == q) continue;
                    float akp = A[k][p], akq = A[k][q];
                    float np = fmaf(c, akp, -s * akq);
                    float nq = fmaf(s, akp, c * akq);
                    A[k][p] = np; A[p][k] = np;
                    A[k][q] = nq; A[q][k] = nq;
                }
            }
        }
    }

    float f = 0.f;
#pragma unroll
    for (int i = 0; i < 8; i++) f += sqrtf(fmaxf(A[i][i], 0.f) + EPSF);
    f = fminf(f, 1.f);
    out[b] = -logf(fmaxf(f, 1e-8f));
}

extern "C" void kernel_launch(void* const* d_in, const int* in_sizes, int n_in,
                              void* d_out, int out_size) {
    const int* contexts = (const int*)d_in[0];
    const int* targets  = (const int*)d_in[1];
    const float* emb    = (const float*)d_in[2];
    float* out          = (float*)d_out;

    int B = in_sizes[1];
    int S = in_sizes[0] / B;

    if (S == 10) {
        int total = B * 4;
        qcbow_quad<<<(total + 127) / 128, 128>>>(contexts, targets, emb, out, B);
    } else {
        int threads = 64;
        qcbow_fallback<<<(B + threads - 1) / threads, threads>>>(contexts, targets, emb, out, B, S);
    }
}

// round 16
// speedup vs baseline: 1.4868x; 1.4868x over previous
#include <cuda_runtime.h>

#define EPSF 1e-6f

__device__ __forceinline__ int tri(int i, int j) { return i * (i + 1) / 2 + j; } // j<=i

// Symmetric 8x8 stored as lower-tri 36; all uses have compile-time indices.
#define AS(i, j) As[((i) >= (j)) ? ((i) * ((i) + 1) / 2 + (j)) : ((j) * ((j) + 1) / 2 + (i))]

// Weighted-accumulate the normalized density matrix of one embedding row into dst[36]:
// dst += w * rho_norm(row). Low register pressure: diag Gram first -> scale, then
// stream off-diagonals straight into dst (no r[36] temp).
__device__ __forceinline__ void density_acc(const float4* __restrict__ row, float w,
                                            float* __restrict__ dst) {
    float p[36];
#pragma unroll
    for (int v = 0; v < 9; v++) {
        float4 q = __ldg(row + v);
        p[4 * v + 0] = q.x; p[4 * v + 1] = q.y; p[4 * v + 2] = q.z; p[4 * v + 3] = q.w;
    }
#pragma unroll
    for (int i = 0; i < 8; i++) p[tri(i, i)] = fmaxf(p[tri(i, i)], 1e-4f);

    // diagonal Gram entries + trace
    float diag[8];
    float trs = 0.f;
#pragma unroll
    for (int i = 0; i < 8; i++) {
        float s = 0.f;
#pragma unroll
        for (int k = 0; k <= i; k++) s = fmaf(p[tri(i, k)], p[tri(i, k)], s);
        diag[i] = s;
        trs += s;
    }
    // corr = 1e-6 always (rho = LL^T + eps*I is PD) -> diag shift eps+1e-6 = 2e-6
    float inv = w * __fdividef(1.f, trs + 8.f * 2e-6f + EPSF);

#pragma unroll
    for (int i = 0; i < 8; i++)
        dst[tri(i, i)] = fmaf(inv, diag[i] + 2e-6f, dst[tri(i, i)]);
#pragma unroll
    for (int i = 1; i < 8; i++) {
#pragma unroll
        for (int j = 0; j < i; j++) {
            float s = 0.f;
#pragma unroll
            for (int k = 0; k <= j; k++) s = fmaf(p[tri(i, k)], p[tri(j, k)], s);
            dst[tri(i, j)] = fmaf(inv, s, dst[tri(i, j)]);
        }
    }
}

// One tournament round of the quad-parallel Jacobi. r must be a compile-time
// constant at every call site (unrolled loops) so all indexing stays in registers.
__device__ __forceinline__ void jround(float* __restrict__ As, int r,
                                       bool is1, bool is2, bool is3) {
    const int JP[7][4] = {{0,1,2,3},{0,2,3,4},{0,1,4,5},{0,2,1,6},{0,3,2,1},{0,4,3,1},{0,5,1,2}};
    const int JQ[7][4] = {{7,6,5,4},{1,7,6,5},{2,3,7,6},{3,4,5,7},{4,5,6,7},{5,6,7,2},{6,7,4,3}};

    // select this lane's (app, aqq, apq) -- compile-time indices + SEL tree
    float app, aqq, apq;
    {
        float x0 = As[tri(JP[r][0], JP[r][0])], x1 = As[tri(JP[r][1], JP[r][1])];
        float x2 = As[tri(JP[r][2], JP[r][2])], x3 = As[tri(JP[r][3], JP[r][3])];
        app = is3 ? x3 : (is2 ? x2 : (is1 ? x1 : x0));
        float y0 = As[tri(JQ[r][0], JQ[r][0])], y1 = As[tri(JQ[r][1], JQ[r][1])];
        float y2 = As[tri(JQ[r][2], JQ[r][2])], y3 = As[tri(JQ[r][3], JQ[r][3])];
        aqq = is3 ? y3 : (is2 ? y2 : (is1 ? y1 : y0));
        float z0 = As[tri(JQ[r][0], JP[r][0])], z1 = As[tri(JQ[r][1], JP[r][1])];
        float z2 = As[tri(JQ[r][2], JP[r][2])], z3 = As[tri(JQ[r][3], JP[r][3])];
        apq = is3 ? z3 : (is2 ? z2 : (is1 ? z1 : z0));
    }
    // one rotation-parameter chain per lane
    float theta = __fdividef(aqq - app, 2.f * apq);
    float t = __fdividef(1.f, fabsf(theta) + sqrtf(fmaf(theta, theta, 1.f)));
    t = copysignf(t, theta);
    t = (fabsf(apq) > 1e-30f) ? t : 0.f;   // also kills NaN theta (0/0)
    float c = rsqrtf(fmaf(t, t, 1.f));
    float s = t * c;
    float d = t * apq;

    // exchange (c, s, d) across the quad
    float cj[4], sj[4], dj[4];
#pragma unroll
    for (int j = 0; j < 4; j++) {
        cj[j] = __shfl_sync(0xffffffffu, c, j, 4);
        sj[j] = __shfl_sync(0xffffffffu, s, j, 4);
        dj[j] = __shfl_sync(0xffffffffu, d, j, 4);
    }

    // every lane applies all 4 disjoint rotations to its copy of As
#pragma unroll
    for (int i = 0; i < 4; i++) {
        int p = JP[r][i], q = JQ[r][i];
        As[tri(p, p)] -= dj[i];
        As[tri(q, q)] += dj[i];
        As[tri(q, p)] = 0.f;                  // p<q
    }
#pragma unroll
    for (int i = 0; i < 4; i++) {
#pragma unroll
        for (int j = i + 1; j < 4; j++) {
            int pi = JP[r][i], qi = JQ[r][i];
            int pj = JP[r][j], qj = JQ[r][j];
            float a00 = AS(pi, pj), a01 = AS(pi, qj);
            float a10 = AS(qi, pj), a11 = AS(qi, qj);
            // rows (G_i^T)
            float b00 = fmaf(cj[i], a00, -sj[i] * a10);
            float b01 = fmaf(cj[i], a01, -sj[i] * a11);
            float b10 = fmaf(sj[i], a00,  cj[i] * a10);
            float b11 = fmaf(sj[i], a01,  cj[i] * a11);
            // cols (G_j)
            float n00 = fmaf(cj[j], b00, -sj[j] * b01);
            float n01 = fmaf(sj[j], b00,  cj[j] * b01);
            float n10 = fmaf(cj[j], b10, -sj[j] * b11);
            float n11 = fmaf(sj[j], b10,  cj[j] * b11);
            AS(pi, pj) = n00; AS(pi, qj) = n01;
            AS(qi, pj) = n10; AS(qi, qj) = n11;
        }
    }
}

// ---------------- cooperative kernel: 4 lanes per batch element ----------------
template <int S>
__global__ void __launch_bounds__(128, 4) qcbow_quad(
    const int* __restrict__ contexts,   // [B, S]
    const int* __restrict__ targets,    // [B]
    const float* __restrict__ emb,      // [V, 36]
    float* __restrict__ out,            // [B]
    int B)
{
    int tid = blockIdx.x * 128 + threadIdx.x;
    int b   = tid >> 2;
    int sub = tid & 3;
    bool active = (b < B);
    if (!active) b = 0;               // keep all lanes alive for shuffles

    // ---- phase 1: context densities split across the quad ----
    float acc[36];
#pragma unroll
    for (int i = 0; i < 36; i++) acc[i] = 0.f;
    float cnt = 0.f;

#pragma unroll
    for (int s0 = 0; s0 < S; s0 += 4) {
        int s = s0 + sub;
        if (s < S) {
            int tok = contexts[b * S + s];
            float w = (tok != 0) ? 1.f : 0.f;
            cnt += w;
            density_acc((const float4*)(emb + (size_t)tok * 36u), w, acc);
        }
    }
    // butterfly reduce within the quad; all 4 lanes end bitwise identical
#pragma unroll
    for (int i = 0; i < 36; i++) {
        acc[i] += __shfl_xor_sync(0xffffffffu, acc[i], 1);
        acc[i] += __shfl_xor_sync(0xffffffffu, acc[i], 2);
    }
    cnt += __shfl_xor_sync(0xffffffffu, cnt, 1);
    cnt += __shfl_xor_sync(0xffffffffu, cnt, 2);

    // ---- Cholesky of rho_bar + eps*I, in place in acc (lower C) ----
    {
        float invc = __fdividef(1.f, cnt);
#pragma unroll
        for (int i = 0; i < 36; i++) acc[i] *= invc;
#pragma unroll
        for (int i = 0; i < 8; i++) acc[tri(i, i)] += EPSF;
#pragma unroll
        for (int j = 0; j < 8; j++) {
            float d = acc[tri(j, j)];
#pragma unroll
            for (int k = 0; k < j; k++) d = fmaf(-acc[tri(j, k)], acc[tri(j, k)], d);
            d = sqrtf(fmaxf(d, 1e-12f));
            acc[tri(j, j)] = d;
            float invd = __fdividef(1.f, d);
#pragma unroll
            for (int i = j + 1; i < 8; i++) {
                float v = acc[tri(i, j)];
#pragma unroll
                for (int k = 0; k < j; k++) v = fmaf(-acc[tri(i, k)], acc[tri(j, k)], v);
                acc[tri(i, j)] = v * invd;
            }
        }
    }

    // ---- target density (replicated; same address -> broadcast loads) ----
    float sigma[36];
#pragma unroll
    for (int i = 0; i < 36; i++) sigma[i] = 0.f;
    density_acc((const float4*)(emb + (size_t)targets[b] * 36u), 1.f, sigma);

    // ---- As = C^T * sigma * C (symmetric, lower-tri storage);
    //      eig(As) = eig((rho_bar+eps I) sigma) ----
    float As[36];
#pragma unroll
    for (int bc = 0; bc < 8; bc++) {
        float tcol[8];
#pragma unroll
        for (int k = 0; k < 8; k++) {
            float s = 0.f;
#pragma unroll
            for (int m = 0; m < 8; m++) {
                if (m < bc) continue;                 // C[m][bc]==0 for m<bc
                float sg = (k >= m) ? sigma[tri(k, m)] : sigma[tri(m, k)];
                s = fmaf(sg, acc[tri(m, bc)], s);
            }
            tcol[k] = s;
        }
#pragma unroll
        for (int a = 0; a <= bc; a++) {
            float s = 0.f;
#pragma unroll
            for (int k = 0; k < 8; k++) {
                if (k < a) continue;                  // C[k][a]==0 for k<a
                s = fmaf(acc[tri(k, a)], tcol[k], s);
            }
            As[tri(bc, a)] = s;
        }
    }

    // ---- quad-parallel Jacobi: 3 full sweeps + 3 hedge rounds (validated rel_err) ----
    bool is1 = (sub == 1), is2 = (sub == 2), is3 = (sub == 3);
#pragma unroll 1
    for (int sweep = 0; sweep < 3; sweep++) {
#pragma unroll
        for (int r = 0; r < 7; r++) jround(As, r, is1, is2, is3);
    }
#pragma unroll
    for (int r = 0; r < 3; r++) jround(As, r, is1, is2, is3);

    // ---- f = sum sqrt(lambda + eps), clip, -log ----
    if (active && sub == 0) {
        float f = 0.f;
#pragma unroll
        for (int i = 0; i < 8; i++) f += sqrtf(fmaxf(As[tri(i, i)], 0.f) + EPSF);
        f = fminf(f, 1.f);
        out[b] = -logf(fmaxf(f, 1e-8f));
    }
}

// ---------------- Fallback: monolithic kernel for unexpected shapes ----------------
__global__ void __launch_bounds__(64) qcbow_fallback(
    const int* __restrict__ contexts, const int* __restrict__ targets,
    const float* __restrict__ emb, float* __restrict__ out, int B, int S)
{
    int b = blockIdx.x * blockDim.x + threadIdx.x;
    if (b >= B) return;

    float acc[36];
#pragma unroll
    for (int i = 0; i < 36; i++) acc[i] = 0.f;
    float cnt = 0.f;
#pragma unroll 1
    for (int s = 0; s < S; s++) {
        int tok = contexts[(long long)b * S + s];
        float w = (tok != 0) ? 1.f : 0.f;
        cnt += w;
        density_acc((const float4*)(emb + (size_t)tok * 36u), w, acc);
    }
    float sigma[36];
#pragma unroll
    for (int i = 0; i < 36; i++) sigma[i] = 0.f;
    density_acc((const float4*)(emb + (size_t)targets[b] * 36u), 1.f, sigma);

    float C[36];
    {
        float invc = __fdividef(1.f, cnt);
#pragma unroll
        for (int i = 0; i < 36; i++) C[i] = acc[i] * invc;
#pragma unroll
        for (int i = 0; i < 8; i++) C[tri(i, i)] += EPSF;
#pragma unroll
        for (int j = 0; j < 8; j++) {
            float d = C[tri(j, j)];
#pragma unroll
            for (int k = 0; k < j; k++) d = fmaf(-C[tri(j, k)], C[tri(j, k)], d);
            d = sqrtf(fmaxf(d, 1e-12f));
            C[tri(j, j)] = d;
            float invd = __fdividef(1.f, d);
#pragma unroll
            for (int i = j + 1; i < 8; i++) {
                float v = C[tri(i, j)];
#pragma unroll
                for (int k = 0; k < j; k++) v = fmaf(-C[tri(i, k)], C[tri(j, k)], v);
                C[tri(i, j)] = v * invd;
            }
        }
    }

    float A[8][8];
#pragma unroll
    for (int bc = 0; bc < 8; bc++) {
        float tcol[8];
#pragma unroll
        for (int k = 0; k < 8; k++) {
            float s = 0.f;
#pragma unroll
            for (int m = 0; m < 8; m++) {
                if (m < bc) continue;
                float sg = (k >= m) ? sigma[tri(k, m)] : sigma[tri(m, k)];
                s = fmaf(sg, C[tri(m, bc)], s);
            }
            tcol[k] = s;
        }
#pragma unroll
        for (int a = 0; a < 8; a++) {
            if (a > bc) continue;
            float s = 0.f;
#pragma unroll
            for (int k = 0; k < 8; k++) {
                if (k < a) continue;
                s = fmaf(C[tri(k, a)], tcol[k], s);
            }
            A[a][bc] = s; A[bc][a] = s;
        }
    }

#pragma unroll 1
    for (int sweep = 0; sweep < 6; sweep++) {
#pragma unroll
        for (int p = 0; p < 7; p++) {
#pragma unroll
            for (int q = p + 1; q < 8; q++) {
                float apq = A[p][q];
                float app = A[p][p], aqq = A[q][q];
                float theta = __fdividef(aqq - app, 2.f * apq);
                float t = __fdividef(1.f, fabsf(theta) + sqrtf(fmaf(theta, theta, 1.f)));
                t = copysignf(t, theta);
                t = (fabsf(apq) > 1e-30f) ? t : 0.f;
                float c = rsqrtf(fmaf(t, t, 1.f));
                float s = t * c;
                A[p][p] = fmaf(-t, apq, app);
                A[q][q] = fmaf(t, apq, aqq);
                A[p][q] = 0.f; A[q][p] = 0.f;
#pragma unroll
                for (int k = 0; k < 8; k++) {
                    if (k == p || k == q) continue;
                    float akp = A[k][p], akq = A[k][q];
                    float np = fmaf(c, akp, -s * akq);
                    float nq = fmaf(s, akp, c * akq);
                    A[k][p] = np; A[p][k] = np;
                    A[k][q] = nq; A[q][k] = nq;
                }
            }
        }
    }

    float f = 0.f;
#pragma unroll
    for (int i = 0; i < 8; i++) f += sqrtf(fmaxf(A[i][i], 0.f) + EPSF);
    f = fminf(f, 1.f);
    out[b] = -logf(fmaxf(f, 1e-8f));
}

extern "C" void kernel_launch(void* const* d_in, const int* in_sizes, int n_in,
                              void* d_out, int out_size) {
    const int* contexts = (const int*)d_in[0];
    const int* targets  = (const int*)d_in[1];
    const float* emb    = (const float*)d_in[2];
    float* out          = (float*)d_out;

    int B = in_sizes[1];
    int S = in_sizes[0] / B;

    if (S == 10) {
        int total = B * 4;
        qcbow_quad<10><<<(total + 127) / 128, 128>>>(contexts, targets, emb, out, B);
    } else {
        int threads = 64;
        qcbow_fallback<<<(B + threads - 1) / threads, threads>>>(contexts, targets, emb, out, B, S);
    }
}

// round 17
// speedup vs baseline: 1.5897x; 1.0692x over previous
#include <cuda_runtime.h>

#define EPSF 1e-6f

__device__ __forceinline__ int tri(int i, int j) { return i * (i + 1) / 2 + j; } // j<=i

// Symmetric 8x8 stored as lower-tri 36; all uses have compile-time indices.
#define AS(i, j) As[((i) >= (j)) ? ((i) * ((i) + 1) / 2 + (j)) : ((j) * ((j) + 1) / 2 + (i))]

// dst (SET? = : +=) w * rho_norm(row). Low register pressure: diag Gram first ->
// trace -> scale, then stream off-diagonals straight into dst (no r[36] temp).
template <bool SET>
__device__ __forceinline__ void density_go(const float4* __restrict__ row, float w,
                                           float* __restrict__ dst) {
    float p[36];
#pragma unroll
    for (int v = 0; v < 9; v++) {
        float4 q = __ldg(row + v);
        p[4 * v + 0] = q.x; p[4 * v + 1] = q.y; p[4 * v + 2] = q.z; p[4 * v + 3] = q.w;
    }
#pragma unroll
    for (int i = 0; i < 8; i++) p[tri(i, i)] = fmaxf(p[tri(i, i)], 1e-4f);

    // diagonal Gram entries + trace
    float diag[8];
    float trs = 0.f;
#pragma unroll
    for (int i = 0; i < 8; i++) {
        float s = 0.f;
#pragma unroll
        for (int k = 0; k <= i; k++) s = fmaf(p[tri(i, k)], p[tri(i, k)], s);
        diag[i] = s;
        trs += s;
    }
    // corr = 1e-6 always (rho = LL^T + eps*I is PD) -> diag shift eps+1e-6 = 2e-6
    float inv = w * __fdividef(1.f, trs + 8.f * 2e-6f + EPSF);

#pragma unroll
    for (int i = 0; i < 8; i++) {
        float v = inv * (diag[i] + 2e-6f);
        dst[tri(i, i)] = SET ? v : fmaf(1.f, v, dst[tri(i, i)]);
    }
#pragma unroll
    for (int i = 1; i < 8; i++) {
#pragma unroll
        for (int j = 0; j < i; j++) {
            float s = 0.f;
#pragma unroll
            for (int k = 0; k <= j; k++) s = fmaf(p[tri(i, k)], p[tri(j, k)], s);
            if (SET) dst[tri(i, j)] = inv * s;
            else     dst[tri(i, j)] = fmaf(inv, s, dst[tri(i, j)]);
        }
    }
}

// One tournament round of the quad-parallel Jacobi. r must be a compile-time
// constant at every call site (unrolled loops) so all indexing stays in registers.
__device__ __forceinline__ void jround(float* __restrict__ As, int r,
                                       bool is1, bool is2, bool is3) {
    const int JP[7][4] = {{0,1,2,3},{0,2,3,4},{0,1,4,5},{0,2,1,6},{0,3,2,1},{0,4,3,1},{0,5,1,2}};
    const int JQ[7][4] = {{7,6,5,4},{1,7,6,5},{2,3,7,6},{3,4,5,7},{4,5,6,7},{5,6,7,2},{6,7,4,3}};

    // select this lane's (app, aqq, apq) -- compile-time indices + SEL tree
    float app, aqq, apq;
    {
        float x0 = As[tri(JP[r][0], JP[r][0])], x1 = As[tri(JP[r][1], JP[r][1])];
        float x2 = As[tri(JP[r][2], JP[r][2])], x3 = As[tri(JP[r][3], JP[r][3])];
        app = is3 ? x3 : (is2 ? x2 : (is1 ? x1 : x0));
        float y0 = As[tri(JQ[r][0], JQ[r][0])], y1 = As[tri(JQ[r][1], JQ[r][1])];
        float y2 = As[tri(JQ[r][2], JQ[r][2])], y3 = As[tri(JQ[r][3], JQ[r][3])];
        aqq = is3 ? y3 : (is2 ? y2 : (is1 ? y1 : y0));
        float z0 = As[tri(JQ[r][0], JP[r][0])], z1 = As[tri(JQ[r][1], JP[r][1])];
        float z2 = As[tri(JQ[r][2], JP[r][2])], z3 = As[tri(JQ[r][3], JP[r][3])];
        apq = is3 ? z3 : (is2 ? z2 : (is1 ? z1 : z0));
    }
    // rotation parameters: t = sign(tau)*apq / (|tau| + sqrt(tau^2 + apq^2)),
    // algebraically equal to the textbook 1/(|theta|+sqrt(theta^2+1)) form.
    float tau = 0.5f * (aqq - app);
    float den = fabsf(tau) + sqrtf(fmaf(tau, tau, apq * apq));
    float t = __fdividef(apq, copysignf(den, tau));
    t = (fabsf(apq) > 1e-30f) ? t : 0.f;   // kills 0/0 NaN when apq=tau=0
    float c = rsqrtf(fmaf(t, t, 1.f));
    float s = t * c;
    float d = t * apq;

    // exchange (c, s, d) across the quad
    float cj[4], sj[4], dj[4];
#pragma unroll
    for (int j = 0; j < 4; j++) {
        cj[j] = __shfl_sync(0xffffffffu, c, j, 4);
        sj[j] = __shfl_sync(0xffffffffu, s, j, 4);
        dj[j] = __shfl_sync(0xffffffffu, d, j, 4);
    }

    // every lane applies all 4 disjoint rotations to its copy of As
#pragma unroll
    for (int i = 0; i < 4; i++) {
        int p = JP[r][i], q = JQ[r][i];
        As[tri(p, p)] -= dj[i];
        As[tri(q, q)] += dj[i];
        As[tri(q, p)] = 0.f;                  // p<q
    }
#pragma unroll
    for (int i = 0; i < 4; i++) {
#pragma unroll
        for (int j = i + 1; j < 4; j++) {
            int pi = JP[r][i], qi = JQ[r][i];
            int pj = JP[r][j], qj = JQ[r][j];
            float a00 = AS(pi, pj), a01 = AS(pi, qj);
            float a10 = AS(qi, pj), a11 = AS(qi, qj);
            // rows (G_i^T)
            float b00 = fmaf(cj[i], a00, -sj[i] * a10);
            float b01 = fmaf(cj[i], a01, -sj[i] * a11);
            float b10 = fmaf(sj[i], a00,  cj[i] * a10);
            float b11 = fmaf(sj[i], a01,  cj[i] * a11);
            // cols (G_j)
            float n00 = fmaf(cj[j], b00, -sj[j] * b01);
            float n01 = fmaf(sj[j], b00,  cj[j] * b01);
            float n10 = fmaf(cj[j], b10, -sj[j] * b11);
            float n11 = fmaf(sj[j], b10,  cj[j] * b11);
            AS(pi, pj) = n00; AS(pi, qj) = n01;
            AS(qi, pj) = n10; AS(qi, qj) = n11;
        }
    }
}

// ---------------- cooperative kernel: 4 lanes per batch element ----------------
template <int S>
__global__ void __launch_bounds__(128, 4) qcbow_quad(
    const int* __restrict__ contexts,   // [B, S]
    const int* __restrict__ targets,    // [B]
    const float* __restrict__ emb,      // [V, 36]
    float* __restrict__ out,            // [B]
    int B)
{
    int tid = blockIdx.x * 128 + threadIdx.x;
    int b   = tid >> 2;
    int sub = tid & 3;
    bool active = (b < B);
    if (!active) b = 0;               // keep all lanes alive for shuffles

    // ---- phase 1: context densities split across the quad ----
    float acc[36];
#pragma unroll
    for (int i = 0; i < 36; i++) acc[i] = 0.f;
    float cnt = 0.f;

#pragma unroll
    for (int s0 = 0; s0 < S; s0 += 4) {
        int s = s0 + sub;
        if (s < S) {
            int tok = contexts[b * S + s];
            float w = (tok != 0) ? 1.f : 0.f;
            cnt += w;
            density_go<false>((const float4*)(emb + (size_t)tok * 36u), w, acc);
        }
    }
    // butterfly reduce within the quad; all 4 lanes end bitwise identical
#pragma unroll
    for (int i = 0; i < 36; i++) {
        acc[i] += __shfl_xor_sync(0xffffffffu, acc[i], 1);
        acc[i] += __shfl_xor_sync(0xffffffffu, acc[i], 2);
    }
    cnt += __shfl_xor_sync(0xffffffffu, cnt, 1);
    cnt += __shfl_xor_sync(0xffffffffu, cnt, 2);

    // ---- Cholesky of rho_bar + eps*I, in place in acc (lower C) ----
    {
        float invc = __fdividef(1.f, cnt);
#pragma unroll
        for (int i = 0; i < 36; i++) acc[i] *= invc;
#pragma unroll
        for (int i = 0; i < 8; i++) acc[tri(i, i)] += EPSF;
#pragma unroll
        for (int j = 0; j < 8; j++) {
            float d = acc[tri(j, j)];
#pragma unroll
            for (int k = 0; k < j; k++) d = fmaf(-acc[tri(j, k)], acc[tri(j, k)], d);
            d = sqrtf(fmaxf(d, 1e-12f));
            acc[tri(j, j)] = d;
            float invd = __fdividef(1.f, d);
#pragma unroll
            for (int i = j + 1; i < 8; i++) {
                float v = acc[tri(i, j)];
#pragma unroll
                for (int k = 0; k < j; k++) v = fmaf(-acc[tri(i, k)], acc[tri(j, k)], v);
                acc[tri(i, j)] = v * invd;
            }
        }
    }

    // ---- target density (replicated; same address -> broadcast loads) ----
    float sigma[36];
    density_go<true>((const float4*)(emb + (size_t)targets[b] * 36u), 1.f, sigma);

    // ---- As = C^T * sigma * C (symmetric, lower-tri storage);
    //      eig(As) = eig((rho_bar+eps I) sigma) ----
    float As[36];
#pragma unroll
    for (int bc = 0; bc < 8; bc++) {
        float tcol[8];
#pragma unroll
        for (int k = 0; k < 8; k++) {
            float s = 0.f;
#pragma unroll
            for (int m = 0; m < 8; m++) {
                if (m < bc) continue;                 // C[m][bc]==0 for m<bc
                float sg = (k >= m) ? sigma[tri(k, m)] : sigma[tri(m, k)];
                s = fmaf(sg, acc[tri(m, bc)], s);
            }
            tcol[k] = s;
        }
#pragma unroll
        for (int a = 0; a <= bc; a++) {
            float s = 0.f;
#pragma unroll
            for (int k = 0; k < 8; k++) {
                if (k < a) continue;                  // C[k][a]==0 for k<a
                s = fmaf(acc[tri(k, a)], tcol[k], s);
            }
            As[tri(bc, a)] = s;
        }
    }

    // ---- quad-parallel Jacobi: 3 full sweeps (21 rounds) ----
    bool is1 = (sub == 1), is2 = (sub == 2), is3 = (sub == 3);
#pragma unroll 1
    for (int sweep = 0; sweep < 3; sweep++) {
#pragma unroll
        for (int r = 0; r < 7; r++) jround(As, r, is1, is2, is3);
    }

    // ---- f = sum sqrt(lambda + eps), clip, -log ----
    if (active && sub == 0) {
        float f = 0.f;
#pragma unroll
        for (int i = 0; i < 8; i++) f += sqrtf(fmaxf(As[tri(i, i)], 0.f) + EPSF);
        f = fminf(f, 1.f);
        out[b] = -logf(fmaxf(f, 1e-8f));
    }
}

// ---------------- Fallback: monolithic kernel for unexpected shapes ----------------
__global__ void __launch_bounds__(64) qcbow_fallback(
    const int* __restrict__ contexts, const int* __restrict__ targets,
    const float* __restrict__ emb, float* __restrict__ out, int B, int S)
{
    int b = blockIdx.x * blockDim.x + threadIdx.x;
    if (b >= B) return;

    float acc[36];
#pragma unroll
    for (int i = 0; i < 36; i++) acc[i] = 0.f;
    float cnt = 0.f;
#pragma unroll 1
    for (int s = 0; s < S; s++) {
        int tok = contexts[(long long)b * S + s];
        float w = (tok != 0) ? 1.f : 0.f;
        cnt += w;
        density_go<false>((const float4*)(emb + (size_t)tok * 36u), w, acc);
    }
    float sigma[36];
    density_go<true>((const float4*)(emb + (size_t)targets[b] * 36u), 1.f, sigma);

    float C[36];
    {
        float invc = __fdividef(1.f, cnt);
#pragma unroll
        for (int i = 0; i < 36; i++) C[i] = acc[i] * invc;
#pragma unroll
        for (int i = 0; i < 8; i++) C[tri(i, i)] += EPSF;
#pragma unroll
        for (int j = 0; j < 8; j++) {
            float d = C[tri(j, j)];
#pragma unroll
            for (int k = 0; k < j; k++) d = fmaf(-C[tri(j, k)], C[tri(j, k)], d);
            d = sqrtf(fmaxf(d, 1e-12f));
            C[tri(j, j)] = d;
            float invd = __fdividef(1.f, d);
#pragma unroll
            for (int i = j + 1; i < 8; i++) {
                float v = C[tri(i, j)];
#pragma unroll
                for (int k = 0; k < j; k++) v = fmaf(-C[tri(i, k)], C[tri(j, k)], v);
                C[tri(i, j)] = v * invd;
            }
        }
    }

    float A[8][8];
#pragma unroll
    for (int bc = 0; bc < 8; bc++) {
        float tcol[8];
#pragma unroll
        for (int k = 0; k < 8; k++) {
            float s = 0.f;
#pragma unroll
            for (int m = 0; m < 8; m++) {
                if (m < bc) continue;
                float sg = (k >= m) ? sigma[tri(k, m)] : sigma[tri(m, k)];
                s = fmaf(sg, C[tri(m, bc)], s);
            }
            tcol[k] = s;
        }
#pragma unroll
        for (int a = 0; a < 8; a++) {
            if (a > bc) continue;
            float s = 0.f;
#pragma unroll
            for (int k = 0; k < 8; k++) {
                if (k < a) continue;
                s = fmaf(C[tri(k, a)], tcol[k], s);
            }
            A[a][bc] = s; A[bc][a] = s;
        }
    }

#pragma unroll 1
    for (int sweep = 0; sweep < 6; sweep++) {
#pragma unroll
        for (int p = 0; p < 7; p++) {
#pragma unroll
            for (int q = p + 1; q < 8; q++) {
                float apq = A[p][q];
                float app = A[p][p], aqq = A[q][q];
                float tau = 0.5f * (aqq - app);
                float den = fabsf(tau) + sqrtf(fmaf(tau, tau, apq * apq));
                float t = __fdividef(apq, copysignf(den, tau));
                t = (fabsf(apq) > 1e-30f) ? t : 0.f;
                float c = rsqrtf(fmaf(t, t, 1.f));
                float s = t * c;
                A[p][p] = fmaf(-t, apq, app);
                A[q][q] = fmaf(t, apq, aqq);
                A[p][q] = 0.f; A[q][p] = 0.f;
#pragma unroll
                for (int k = 0; k < 8; k++) {
                    if (k == p || k == q) continue;
                    float akp = A[k][p], akq = A[k][q];
                    float np = fmaf(c, akp, -s * akq);
                    float nq = fmaf(s, akp, c * akq);
                    A[k][p] = np; A[p][k] = np;
                    A[k][q] = nq; A[q][k] = nq;
                }
            }
        }
    }

    float f = 0.f;
#pragma unroll
    for (int i = 0; i < 8; i++) f += sqrtf(fmaxf(A[i][i], 0.f) + EPSF);
    f = fminf(f, 1.f);
    out[b] = -logf(fmaxf(f, 1e-8f));
}

extern "C" void kernel_launch(void* const* d_in, const int* in_sizes, int n_in,
                              void* d_out, int out_size) {
    const int* contexts = (const int*)d_in[0];
    const int* targets  = (const int*)d_in[1];
    const float* emb    = (const float*)d_in[2];
    float* out          = (float*)d_out;

    int B = in_sizes[1];
    int S = in_sizes[0] / B;

    if (S == 10) {
        int total = B * 4;
        qcbow_quad<10><<<(total + 127) / 128, 128>>>(contexts, targets, emb, out, B);
    } else {
        int threads = 64;
        qcbow_fallback<<<(B + threads - 1) / threads, threads>>>(contexts, targets, emb, out, B, S);
    }
}